// round 5
// baseline (speedup 1.0000x reference)
#include <cuda_runtime.h>
#include <math.h>

#define N_NODES 50000
#define N_EDGES 800000
#define DIN 64
#define DH 128
#define DOUT 64
#define EPW 4   // edges per warp per iteration

// Scratch: per-node factored layer-0 partials (A = x@W0[:64], B = x@W0[64:] + b0)
__device__ float g_A[N_NODES * DH];
__device__ float g_B[N_NODES * DH];

__device__ __forceinline__ float softplus_f(float x) {
    // stable: max(x,0) + log1p(exp(-|x|)); fast-math variants are well within 1e-3
    return fmaxf(x, 0.0f) + __logf(1.0f + __expf(-fabsf(x)));
}

__global__ void zero_out_kernel(float* __restrict__ out, int n) {
    int i = blockIdx.x * blockDim.x + threadIdx.x;
    if (i < n) out[i] = 0.0f;
}

// Per-node precompute: A[n][j] = sum_{k<64} x[n][k] * W0[k][j]
//                      B[n][j] = b0[j] + sum_{k<64} x[n][k] * W0[64+k][j]
__global__ __launch_bounds__(256, 2)
void precompute_kernel(const float* __restrict__ x,
                       const float* __restrict__ W0,
                       const float* __restrict__ b0) {
    extern __shared__ float smem[];
    float* W0s = smem;            // 128*128
    float* b0s = smem + DH * DH;  // 128
    for (int i = threadIdx.x; i < DH * DH; i += blockDim.x) W0s[i] = W0[i];
    for (int i = threadIdx.x; i < DH; i += blockDim.x) b0s[i] = b0[i];
    __syncthreads();

    const int lane = threadIdx.x & 31;
    const int warp = threadIdx.x >> 5;
    const int nwarps = blockDim.x >> 5;

    for (int n = blockIdx.x * nwarps + warp; n < N_NODES; n += gridDim.x * nwarps) {
        float xr[2];
        xr[0] = x[n * DIN + lane];
        xr[1] = x[n * DIN + 32 + lane];
        float accA[4], accB[4];
        #pragma unroll
        for (int u = 0; u < 4; u++) { accA[u] = 0.0f; accB[u] = b0s[lane + 32 * u]; }
        for (int t = 0; t < 32; t++) {
            #pragma unroll
            for (int s = 0; s < 2; s++) {
                float xv = __shfl_sync(0xffffffffu, xr[s], t);
                int k = s * 32 + t;
                #pragma unroll
                for (int u = 0; u < 4; u++) {
                    accA[u] += xv * W0s[k * DH + lane + 32 * u];
                    accB[u] += xv * W0s[(64 + k) * DH + lane + 32 * u];
                }
            }
        }
        #pragma unroll
        for (int u = 0; u < 4; u++) {
            g_A[(size_t)n * DH + lane + 32 * u] = accA[u];
            g_B[(size_t)n * DH + lane + 32 * u] = accB[u];
        }
    }
}

// Edge MLP + scatter. Warp processes EPW edges per iteration; weights in smem.
// NOTE: edge_idx arrives as int32 (JAX x64 disabled downcasts the declared int64).
__global__ __launch_bounds__(256, 2)
void edge_kernel(const int* __restrict__ eidx,
                 const float* __restrict__ W1,
                 const float* __restrict__ b1,
                 const float* __restrict__ W2,
                 const float* __restrict__ b2,
                 float* __restrict__ out) {
    extern __shared__ float smem[];
    float* W1s = smem;               // 128*128 = 16384
    float* W2s = W1s + DH * DH;      // 128*64  = 8192
    float* b1s = W2s + DH * DOUT;    // 128
    float* b2s = b1s + DH;           // 64
    for (int i = threadIdx.x; i < DH * DH; i += blockDim.x) W1s[i] = W1[i];
    for (int i = threadIdx.x; i < DH * DOUT; i += blockDim.x) W2s[i] = W2[i];
    for (int i = threadIdx.x; i < DH; i += blockDim.x) b1s[i] = b1[i];
    for (int i = threadIdx.x; i < DOUT; i += blockDim.x) b2s[i] = b2[i];
    __syncthreads();

    const int lane = threadIdx.x & 31;
    const int warp = threadIdx.x >> 5;
    const int nwarps = blockDim.x >> 5;
    const int gw = blockIdx.x * nwarps + warp;
    const int gstride = gridDim.x * nwarps;
    const int ngroups = (N_EDGES + EPW - 1) / EPW;

    for (int g = gw; g < ngroups; g += gstride) {
        const int e0 = g * EPW;
        int rows[EPW];
        bool valid[EPW];
        float h0[EPW][4];

        // gather A[row] + B[col], softplus  (h0 layout: k = s*32 + lane)
        #pragma unroll
        for (int ei = 0; ei < EPW; ei++) {
            int e = e0 + ei;
            valid[ei] = (e < N_EDGES);
            int r = 0, c = 0;
            if (valid[ei]) {
                r = eidx[e];               // row (source) index, int32
                c = eidx[N_EDGES + e];     // col (target) index, int32
            }
            rows[ei] = r;
            const float* Ar = g_A + (size_t)r * DH;
            const float* Bc = g_B + (size_t)c * DH;
            #pragma unroll
            for (int s = 0; s < 4; s++)
                h0[ei][s] = softplus_f(Ar[s * 32 + lane] + Bc[s * 32 + lane]);
        }

        // layer 1: output j = 4*lane + u, weight reads via LDS.128
        float acc1[EPW][4];
        {
            float4 bb = *(const float4*)&b1s[4 * lane];
            #pragma unroll
            for (int ei = 0; ei < EPW; ei++) {
                acc1[ei][0] = bb.x; acc1[ei][1] = bb.y;
                acc1[ei][2] = bb.z; acc1[ei][3] = bb.w;
            }
        }
        for (int t = 0; t < 32; t++) {
            #pragma unroll
            for (int s = 0; s < 4; s++) {
                int k = s * 32 + t;
                float4 w = *(const float4*)&W1s[k * DH + 4 * lane];
                #pragma unroll
                for (int ei = 0; ei < EPW; ei++) {
                    float hv = __shfl_sync(0xffffffffu, h0[ei][s], t);
                    acc1[ei][0] += hv * w.x; acc1[ei][1] += hv * w.y;
                    acc1[ei][2] += hv * w.z; acc1[ei][3] += hv * w.w;
                }
            }
        }
        float h1[EPW][4];  // layout: j = 4*lane + u
        #pragma unroll
        for (int ei = 0; ei < EPW; ei++)
            #pragma unroll
            for (int u = 0; u < 4; u++) h1[ei][u] = softplus_f(acc1[ei][u]);

        // layer 2: output j = 2*lane + u (64 outputs), weight reads via LDS.64
        float acc2[EPW][2];
        {
            float2 bb = *(const float2*)&b2s[2 * lane];
            #pragma unroll
            for (int ei = 0; ei < EPW; ei++) { acc2[ei][0] = bb.x; acc2[ei][1] = bb.y; }
        }
        for (int k4 = 0; k4 < 32; k4++) {
            #pragma unroll
            for (int u4 = 0; u4 < 4; u4++) {
                int k = 4 * k4 + u4;  // h1[k] lives at lane k4, register u4
                float2 w = *(const float2*)&W2s[k * DOUT + 2 * lane];
                #pragma unroll
                for (int ei = 0; ei < EPW; ei++) {
                    float hv = __shfl_sync(0xffffffffu, h1[ei][u4], k4);
                    acc2[ei][0] += hv * w.x; acc2[ei][1] += hv * w.y;
                }
            }
        }

        // scatter-add to source nodes
        #pragma unroll
        for (int ei = 0; ei < EPW; ei++) {
            if (valid[ei]) {
                float* o = out + (size_t)rows[ei] * DOUT + 2 * lane;
                atomicAdd(o, acc2[ei][0]);
                atomicAdd(o + 1, acc2[ei][1]);
            }
        }
    }
}

extern "C" void kernel_launch(void* const* d_in, const int* in_sizes, int n_in,
                              void* d_out, int out_size) {
    // Inputs (metadata order): x, edge_idx(int32 — JAX x64-disabled downcast), W0, b0, W1, b1, W2, b2
    const float* x = (const float*)d_in[0];
    const int* eidx = (const int*)d_in[1];
    const float* W0 = (const float*)d_in[2];
    const float* b0 = (const float*)d_in[3];
    const float* W1 = (const float*)d_in[4];
    const float* b1 = (const float*)d_in[5];
    const float* W2 = (const float*)d_in[6];
    const float* b2 = (const float*)d_in[7];
    float* out = (float*)d_out;

    const int pre_smem = (DH * DH + DH) * sizeof(float);                       // ~64.5 KB
    const int edge_smem = (DH * DH + DH * DOUT + DH + DOUT) * sizeof(float);   // ~96.75 KB
    cudaFuncSetAttribute(precompute_kernel, cudaFuncAttributeMaxDynamicSharedMemorySize, pre_smem);
    cudaFuncSetAttribute(edge_kernel, cudaFuncAttributeMaxDynamicSharedMemorySize, edge_smem);

    // 1) zero output (graph replays must not accumulate; d_out is poisoned)
    zero_out_kernel<<<(out_size + 255) / 256, 256>>>(out, out_size);

    // 2) per-node layer-0 factorization
    precompute_kernel<<<296, 256, pre_smem>>>(x, W0, b0);

    // 3) edge MLP + scatter (persistent grid, 2 CTAs/SM target)
    edge_kernel<<<296, 256, edge_smem>>>(eidx, W1, b1, W2, b2, out);
}

// round 6
// speedup vs baseline: 1.4886x; 1.4886x over previous
#include <cuda_runtime.h>
#include <math.h>

#define N_NODES 50000
#define N_EDGES 800000
#define DIN 64
#define DH 128
#define DOUT 64
#define TILE_E 128
#define N_TILES (N_EDGES / TILE_E)   // 6250, exact
#define H_STRIDE 132                 // padded row stride (floats): frag reads land on bank=lane

// Per-node factored layer-0 partials (A = x@W0[:64], B = x@W0[64:] + b0), fp32 exact.
__device__ float4 g_A4[N_NODES * DH / 4];
__device__ float4 g_B4[N_NODES * DH / 4];

__device__ __forceinline__ float softplus_f(float x) {
    return fmaxf(x, 0.0f) + __logf(1.0f + __expf(-fabsf(x)));
}
__device__ __forceinline__ unsigned tf32_rna(float x) {
    unsigned u; asm("cvt.rna.tf32.f32 %0, %1;" : "=r"(u) : "f"(x)); return u;
}
__device__ __forceinline__ void mma_tf32(float d[4], const unsigned a[4], unsigned b0, unsigned b1) {
    asm volatile(
        "mma.sync.aligned.m16n8k8.row.col.f32.tf32.tf32.f32 "
        "{%0,%1,%2,%3}, {%4,%5,%6,%7}, {%8,%9}, {%0,%1,%2,%3};"
        : "+f"(d[0]), "+f"(d[1]), "+f"(d[2]), "+f"(d[3])
        : "r"(a[0]), "r"(a[1]), "r"(a[2]), "r"(a[3]), "r"(b0), "r"(b1));
}
__device__ __forceinline__ void red_add_f2(float* p, float x, float y) {
    asm volatile("red.global.add.v2.f32 [%0], {%1,%2};" :: "l"(p), "f"(x), "f"(y) : "memory");
}

__global__ void zero_out_kernel(float* __restrict__ out, int n) {
    int i = blockIdx.x * blockDim.x + threadIdx.x;
    if (i < n) out[i] = 0.0f;
}

// Per-node precompute (fp32 exact): A[n] = x[n]@W0[:64], B[n] = x[n]@W0[64:] + b0
__global__ __launch_bounds__(256, 2)
void precompute_kernel(const float* __restrict__ x,
                       const float* __restrict__ W0,
                       const float* __restrict__ b0) {
    extern __shared__ float smem[];
    float* W0s = smem;
    float* b0s = smem + 2 * DIN * DH;
    for (int i = threadIdx.x; i < 2 * DIN * DH; i += blockDim.x) W0s[i] = W0[i];
    for (int i = threadIdx.x; i < DH; i += blockDim.x) b0s[i] = b0[i];
    __syncthreads();

    const int lane = threadIdx.x & 31;
    const int warp = threadIdx.x >> 5;
    const int nwarps = blockDim.x >> 5;
    float* gA = (float*)g_A4;
    float* gB = (float*)g_B4;

    for (int n = blockIdx.x * nwarps + warp; n < N_NODES; n += gridDim.x * nwarps) {
        float xr[2];
        xr[0] = x[n * DIN + lane];
        xr[1] = x[n * DIN + 32 + lane];
        float accA[4], accB[4];
        #pragma unroll
        for (int u = 0; u < 4; u++) { accA[u] = 0.0f; accB[u] = b0s[lane + 32 * u]; }
        for (int t = 0; t < 32; t++) {
            #pragma unroll
            for (int s = 0; s < 2; s++) {
                float xv = __shfl_sync(0xffffffffu, xr[s], t);
                int k = s * 32 + t;
                #pragma unroll
                for (int u = 0; u < 4; u++) {
                    accA[u] += xv * W0s[k * DH + lane + 32 * u];
                    accB[u] += xv * W0s[(64 + k) * DH + lane + 32 * u];
                }
            }
        }
        #pragma unroll
        for (int u = 0; u < 4; u++) {
            gA[(size_t)n * DH + lane + 32 * u] = accA[u];
            gB[(size_t)n * DH + lane + 32 * u] = accB[u];
        }
    }
}

// Tensor-core edge kernel: tile of 128 edges per CTA iteration.
// GEMM1: H1 = softplus(H0 @ W1 + b1)  (128x128x128, tf32)
// GEMM2: O  = H1 @ W2 + b2            (128x64x128, tf32), scatter via red.global.v2
__global__ __launch_bounds__(256, 1)
void edge_kernel(const int* __restrict__ eidx,
                 const float* __restrict__ W1,
                 const float* __restrict__ b1,
                 const float* __restrict__ W2,
                 const float* __restrict__ b2,
                 float* __restrict__ out) {
    extern __shared__ unsigned char smem_raw[];
    unsigned* Hs = (unsigned*)smem_raw;                     // 128*132 u32 = 67584 B
    uint2* W1p = (uint2*)(Hs + TILE_E * H_STRIDE);          // 16*16*32 uint2 = 65536 B
    uint2* W2p = W1p + 16 * 16 * 32;                        // 16*8*32 uint2 = 32768 B
    float* b1s = (float*)(W2p + 16 * 8 * 32);               // 512 B
    float* b2s = b1s + DH;                                  // 256 B
    int* rows_s = (int*)(b2s + DOUT);                       // 512 B
    int* cols_s = rows_s + TILE_E;                          // 512 B

    const int tid = threadIdx.x;
    const int lane = tid & 31;
    const int w = tid >> 5;
    const int g = lane >> 2;     // fragment row-in-8
    const int tig = lane & 3;    // fragment thread-in-group
    const int mb = 16 * w;       // warp's 16-edge slice

    // One-time per CTA: fragment-permuted weights (tf32-rounded) + biases.
    // b-frag for m16n8k8: b0 = B[k=tig][n=grp], b1 = B[k=tig+4][n=grp]
    for (int i = tid; i < 16 * 16 * 32; i += 256) {
        int li = i & 31, nt = (i >> 5) & 15, kt = i >> 9;
        int k0 = kt * 8 + (li & 3), n = nt * 8 + (li >> 2);
        uint2 v;
        v.x = tf32_rna(W1[k0 * DH + n]);
        v.y = tf32_rna(W1[(k0 + 4) * DH + n]);
        W1p[i] = v;
    }
    for (int i = tid; i < 16 * 8 * 32; i += 256) {
        int li = i & 31, nt = (i >> 5) & 7, kt = i >> 8;
        int k0 = kt * 8 + (li & 3), n = nt * 8 + (li >> 2);
        uint2 v;
        v.x = tf32_rna(W2[k0 * DOUT + n]);
        v.y = tf32_rna(W2[(k0 + 4) * DOUT + n]);
        W2p[i] = v;
    }
    if (tid < DH) b1s[tid] = b1[tid];
    if (tid < DOUT) b2s[tid] = b2[tid];
    __syncthreads();

    for (int tile = blockIdx.x; tile < N_TILES; tile += gridDim.x) {
        const int e0 = tile * TILE_E;

        // ---- indices ----
        if (tid < TILE_E) {
            rows_s[tid] = eidx[e0 + tid];
            cols_s[tid] = eidx[N_EDGES + e0 + tid];
        }
        __syncthreads();

        // ---- gather + softplus -> H0 (tf32 bits), warp w fills rows mb..mb+15 ----
        #pragma unroll 4
        for (int i = 0; i < 16; i++) {
            int e = mb + i;
            float4 a = g_A4[(size_t)rows_s[e] * 32 + lane];
            float4 bv = g_B4[(size_t)cols_s[e] * 32 + lane];
            uint4 h;
            h.x = tf32_rna(softplus_f(a.x + bv.x));
            h.y = tf32_rna(softplus_f(a.y + bv.y));
            h.z = tf32_rna(softplus_f(a.z + bv.z));
            h.w = tf32_rna(softplus_f(a.w + bv.w));
            *(uint4*)&Hs[e * H_STRIDE + 4 * lane] = h;
        }
        __syncthreads();

        // ---- GEMM1: D1[16 edges x 128] = H0 @ W1 + b1 ----
        float d1[16][4];
        #pragma unroll
        for (int nt = 0; nt < 16; nt++) {
            float2 bb = *(const float2*)&b1s[nt * 8 + 2 * tig];
            d1[nt][0] = bb.x; d1[nt][1] = bb.y; d1[nt][2] = bb.x; d1[nt][3] = bb.y;
        }
        #pragma unroll
        for (int kt = 0; kt < 16; kt++) {
            unsigned a[4];
            int r0 = (mb + g) * H_STRIDE + kt * 8 + tig;
            int r1 = (mb + g + 8) * H_STRIDE + kt * 8 + tig;
            a[0] = Hs[r0]; a[1] = Hs[r1]; a[2] = Hs[r0 + 4]; a[3] = Hs[r1 + 4];
            #pragma unroll
            for (int nt = 0; nt < 16; nt++) {
                uint2 b = W1p[(kt * 16 + nt) * 32 + lane];
                mma_tf32(d1[nt], a, b.x, b.y);
            }
        }
        __syncthreads();  // all H0 reads complete before overwrite

        // ---- softplus + tf32, write H1 into same buffer ----
        // D frag: c0,c1 at (row g, col 2tig+{0,1}); c2,c3 at row g+8.
        #pragma unroll
        for (int nt = 0; nt < 16; nt++) {
            uint2 lo, hi;
            lo.x = tf32_rna(softplus_f(d1[nt][0]));
            lo.y = tf32_rna(softplus_f(d1[nt][1]));
            hi.x = tf32_rna(softplus_f(d1[nt][2]));
            hi.y = tf32_rna(softplus_f(d1[nt][3]));
            *(uint2*)&Hs[(mb + g) * H_STRIDE + nt * 8 + 2 * tig] = lo;
            *(uint2*)&Hs[(mb + g + 8) * H_STRIDE + nt * 8 + 2 * tig] = hi;
        }
        __syncthreads();

        // ---- GEMM2: D2[16 edges x 64] = H1 @ W2 + b2 ----
        float d2[8][4];
        #pragma unroll
        for (int nt = 0; nt < 8; nt++) {
            float2 bb = *(const float2*)&b2s[nt * 8 + 2 * tig];
            d2[nt][0] = bb.x; d2[nt][1] = bb.y; d2[nt][2] = bb.x; d2[nt][3] = bb.y;
        }
        #pragma unroll
        for (int kt = 0; kt < 16; kt++) {
            unsigned a[4];
            int r0 = (mb + g) * H_STRIDE + kt * 8 + tig;
            int r1 = (mb + g + 8) * H_STRIDE + kt * 8 + tig;
            a[0] = Hs[r0]; a[1] = Hs[r1]; a[2] = Hs[r0 + 4]; a[3] = Hs[r1 + 4];
            #pragma unroll
            for (int nt = 0; nt < 8; nt++) {
                uint2 b = W2p[(kt * 8 + nt) * 32 + lane];
                mma_tf32(d2[nt], a, b.x, b.y);
            }
        }

        // ---- scatter-add (fire-and-forget vector reductions) ----
        {
            int r0 = rows_s[mb + g];
            int r1 = rows_s[mb + g + 8];
            #pragma unroll
            for (int nt = 0; nt < 8; nt++) {
                red_add_f2(&out[(size_t)r0 * DOUT + nt * 8 + 2 * tig], d2[nt][0], d2[nt][1]);
                red_add_f2(&out[(size_t)r1 * DOUT + nt * 8 + 2 * tig], d2[nt][2], d2[nt][3]);
            }
        }
        __syncthreads();  // protect rows_s/Hs before next tile
    }
}

extern "C" void kernel_launch(void* const* d_in, const int* in_sizes, int n_in,
                              void* d_out, int out_size) {
    // Inputs: x, edge_idx(int32), W0, b0, W1, b1, W2, b2
    const float* x = (const float*)d_in[0];
    const int* eidx = (const int*)d_in[1];
    const float* W0 = (const float*)d_in[2];
    const float* b0 = (const float*)d_in[3];
    const float* W1 = (const float*)d_in[4];
    const float* b1 = (const float*)d_in[5];
    const float* W2 = (const float*)d_in[6];
    const float* b2 = (const float*)d_in[7];
    float* out = (float*)d_out;

    const int pre_smem = (2 * DIN * DH + DH) * sizeof(float);
    const int edge_smem = TILE_E * H_STRIDE * 4   // Hs      67584
                        + 16 * 16 * 32 * 8       // W1p     65536
                        + 16 * 8 * 32 * 8        // W2p     32768
                        + DH * 4 + DOUT * 4      // biases    768
                        + 2 * TILE_E * 4;        // indices  1024
    cudaFuncSetAttribute(precompute_kernel, cudaFuncAttributeMaxDynamicSharedMemorySize, pre_smem);
    cudaFuncSetAttribute(edge_kernel, cudaFuncAttributeMaxDynamicSharedMemorySize, edge_smem);

    zero_out_kernel<<<(out_size + 255) / 256, 256>>>(out, out_size);
    precompute_kernel<<<296, 256, pre_smem>>>(x, W0, b0);
    edge_kernel<<<148, 256, edge_smem>>>(eidx, W1, b1, W2, b2, out);
}

// round 10
// speedup vs baseline: 2.7726x; 1.8625x over previous
#include <cuda_runtime.h>
#include <cuda_bf16.h>
#include <math.h>

#define N_NODES 50000
#define N_EDGES 800000
#define DIN 64
#define DH 128
#define DOUT 64
#define TILE_E 128
#define N_TILES (N_EDGES / TILE_E)   // 6250 exact
#define HSTRIDE 68                   // u32 pair-stride per H row (bank = 4g+tig, conflict-free)

// ---- edge-kernel SMEM layout (bytes) ----
#define SM_W1H 0                      // 8kt*16nt*32 uint2 = 32768
#define SM_W1L 32768                  // 32768
#define SM_W2H 65536                  // 8kt*8nt*32 uint2 = 16384
#define SM_W2L 81920                  // 16384
#define SM_HHI 98304                  // 128*68*4 = 34816
#define SM_HLO 133120                 // 34816
#define SM_B1  167936                 // 128 f32
#define SM_B2  168448                 // 64 f32
#define SM_TOTAL 168704

// Per-node factored layer-0 partials (A = x@W0[:64], B = x@W0[64:] + b0), fp32 exact.
__device__ float4 g_A4[N_NODES * DH / 4];
__device__ float4 g_B4[N_NODES * DH / 4];

__device__ __forceinline__ float softplus_f(float x) {
    return fmaxf(x, 0.0f) + __logf(1.0f + __expf(-fabsf(x)));
}
// pack two f32 into bf16x2: lo half = a (even k), hi half = b (odd k)
__device__ __forceinline__ unsigned pack_bf2(float a, float b) {
    unsigned d; asm("cvt.rn.bf16x2.f32 %0, %1, %2;" : "=r"(d) : "f"(b), "f"(a)); return d;
}
// hi/lo split of a k-pair
__device__ __forceinline__ void split_pair(float h0, float h1, unsigned& hi, unsigned& lo) {
    hi = pack_bf2(h0, h1);
    float r0 = h0 - __uint_as_float(hi << 16);
    float r1 = h1 - __uint_as_float(hi & 0xffff0000u);
    lo = pack_bf2(r0, r1);
}
// m16n8k16 row.col f32.bf16.bf16.f32 (sm_80 baseline ISA -> real HMMA on sm_103)
__device__ __forceinline__ void mma_bf16(float* d, const unsigned* a, uint2 b) {
    asm volatile(
        "mma.sync.aligned.m16n8k16.row.col.f32.bf16.bf16.f32 "
        "{%0,%1,%2,%3}, {%4,%5,%6,%7}, {%8,%9}, {%0,%1,%2,%3};"
        : "+f"(d[0]), "+f"(d[1]), "+f"(d[2]), "+f"(d[3])
        : "r"(a[0]), "r"(a[1]), "r"(a[2]), "r"(a[3]), "r"(b.x), "r"(b.y));
}
__device__ __forceinline__ void red_add_f2(float* p, float x, float y) {
    asm volatile("red.global.add.v2.f32 [%0], {%1,%2};" :: "l"(p), "f"(x), "f"(y) : "memory");
}

__global__ void zero_out_kernel(float* __restrict__ out, int n) {
    int i = blockIdx.x * blockDim.x + threadIdx.x;
    if (i < n) out[i] = 0.0f;
}

// Per-node precompute (fp32 exact): A[n] = x[n]@W0[:64], B[n] = x[n]@W0[64:] + b0
__global__ __launch_bounds__(256, 2)
void precompute_kernel(const float* __restrict__ x,
                       const float* __restrict__ W0,
                       const float* __restrict__ b0) {
    extern __shared__ float smem[];
    float* W0s = smem;
    float* b0s = smem + 2 * DIN * DH;
    for (int i = threadIdx.x; i < 2 * DIN * DH; i += blockDim.x) W0s[i] = W0[i];
    for (int i = threadIdx.x; i < DH; i += blockDim.x) b0s[i] = b0[i];
    __syncthreads();

    const int lane = threadIdx.x & 31;
    const int warp = threadIdx.x >> 5;
    const int nwarps = blockDim.x >> 5;
    float* gA = (float*)g_A4;
    float* gB = (float*)g_B4;

    for (int n = blockIdx.x * nwarps + warp; n < N_NODES; n += gridDim.x * nwarps) {
        float xr[2];
        xr[0] = x[n * DIN + lane];
        xr[1] = x[n * DIN + 32 + lane];
        float accA[4], accB[4];
        #pragma unroll
        for (int u = 0; u < 4; u++) { accA[u] = 0.0f; accB[u] = b0s[lane + 32 * u]; }
        for (int t = 0; t < 32; t++) {
            #pragma unroll
            for (int s = 0; s < 2; s++) {
                float xv = __shfl_sync(0xffffffffu, xr[s], t);
                int k = s * 32 + t;
                #pragma unroll
                for (int u = 0; u < 4; u++) {
                    accA[u] += xv * W0s[k * DH + lane + 32 * u];
                    accB[u] += xv * W0s[(64 + k) * DH + lane + 32 * u];
                }
            }
        }
        #pragma unroll
        for (int u = 0; u < 4; u++) {
            gA[(size_t)n * DH + lane + 32 * u] = accA[u];
            gB[(size_t)n * DH + lane + 32 * u] = accB[u];
        }
    }
}

// Edge kernel: per warp-tile (16 edges), sync-free across warps.
// H0 = softplus(A[r]+B[c]) hi/lo -> warp-private smem pair-planes;
// GEMM1 (3-term bf16 HMMA) -> D1 regs; softplus -> GEMM2 A-frags in regs;
// GEMM2 (3-term) -> red.global.v2 scatter.
__global__ __launch_bounds__(256)
void edge_kernel(const int* __restrict__ eidx,
                 const float* __restrict__ W1,
                 const float* __restrict__ b1,
                 const float* __restrict__ W2,
                 const float* __restrict__ b2,
                 float* __restrict__ out) {
    extern __shared__ unsigned char smem_uc[];
    uint2* W1ph = (uint2*)(smem_uc + SM_W1H);
    uint2* W1pl = (uint2*)(smem_uc + SM_W1L);
    uint2* W2ph = (uint2*)(smem_uc + SM_W2H);
    uint2* W2pl = (uint2*)(smem_uc + SM_W2L);
    unsigned* Hhi = (unsigned*)(smem_uc + SM_HHI);
    unsigned* Hlo = (unsigned*)(smem_uc + SM_HLO);
    float* b1s = (float*)(smem_uc + SM_B1);
    float* b2s = (float*)(smem_uc + SM_B2);

    const int tid = threadIdx.x;
    const int lane = tid & 31;
    const int w = tid >> 5;
    const int g = lane >> 2;    // fragment group (row-in-8)
    const int tig = lane & 3;   // thread-in-group (k/col pair selector)
    const int mb = 16 * w;      // warp's 16-edge row block

    // ---- one-time weight prep: hi/lo bf16 b-fragments, 1 uint2 per (kt,nt,lane) ----
    for (int i = tid; i < 8 * 16 * 32; i += 256) {
        int li = i & 31, nt = (i >> 5) & 15, kt = i >> 9;
        int k0 = kt * 16 + 2 * (li & 3), n = nt * 8 + (li >> 2);
        float v00 = W1[k0 * DH + n],       v01 = W1[(k0 + 1) * DH + n];
        float v08 = W1[(k0 + 8) * DH + n], v09 = W1[(k0 + 9) * DH + n];
        uint2 hi, lo;
        split_pair(v00, v01, hi.x, lo.x);
        split_pair(v08, v09, hi.y, lo.y);
        W1ph[i] = hi; W1pl[i] = lo;
    }
    for (int i = tid; i < 8 * 8 * 32; i += 256) {
        int li = i & 31, nt = (i >> 5) & 7, kt = i >> 8;
        int k0 = kt * 16 + 2 * (li & 3), n = nt * 8 + (li >> 2);
        float v00 = W2[k0 * DOUT + n],       v01 = W2[(k0 + 1) * DOUT + n];
        float v08 = W2[(k0 + 8) * DOUT + n], v09 = W2[(k0 + 9) * DOUT + n];
        uint2 hi, lo;
        split_pair(v00, v01, hi.x, lo.x);
        split_pair(v08, v09, hi.y, lo.y);
        W2ph[i] = hi; W2pl[i] = lo;
    }
    if (tid < DH) b1s[tid] = b1[tid];
    if (tid < DOUT) b2s[tid] = b2[tid];
    __syncthreads();

    for (int tile = blockIdx.x; tile < N_TILES; tile += gridDim.x) {
        const int e0 = tile * TILE_E + mb;
        // lanes 0-15 hold row idx, 16-31 hold col idx for this warp's 16 edges
        int idx = (lane < 16) ? eidx[e0 + lane] : eidx[N_EDGES + e0 + (lane - 16)];

        // ---- gather + softplus + hi/lo split -> warp-private H planes ----
        #pragma unroll 4
        for (int i = 0; i < 16; i++) {
            int r = __shfl_sync(0xffffffffu, idx, i);
            int c = __shfl_sync(0xffffffffu, idx, 16 + i);
            float4 a = g_A4[(size_t)r * 32 + lane];
            float4 b = g_B4[(size_t)c * 32 + lane];
            float h0 = softplus_f(a.x + b.x);
            float h1 = softplus_f(a.y + b.y);
            float h2 = softplus_f(a.z + b.z);
            float h3 = softplus_f(a.w + b.w);
            uint2 hi, lo;
            split_pair(h0, h1, hi.x, lo.x);
            split_pair(h2, h3, hi.y, lo.y);
            *(uint2*)&Hhi[(mb + i) * HSTRIDE + 2 * lane] = hi;
            *(uint2*)&Hlo[(mb + i) * HSTRIDE + 2 * lane] = lo;
        }
        __syncwarp();

        // ---- GEMM1: D1[16 x 128] = H0 @ W1 + b1 (3-term compensated) ----
        float d1[16][4];
        #pragma unroll
        for (int nt = 0; nt < 16; nt++) {
            float2 bb = *(const float2*)&b1s[nt * 8 + 2 * tig];
            d1[nt][0] = bb.x; d1[nt][1] = bb.y; d1[nt][2] = bb.x; d1[nt][3] = bb.y;
        }
        #pragma unroll
        for (int kt = 0; kt < 8; kt++) {
            int base = (mb + g) * HSTRIDE + 8 * kt + tig;
            unsigned ah[4], al[4];
            ah[0] = Hhi[base];                ah[1] = Hhi[base + 8 * HSTRIDE];
            ah[2] = Hhi[base + 4];            ah[3] = Hhi[base + 8 * HSTRIDE + 4];
            al[0] = Hlo[base];                al[1] = Hlo[base + 8 * HSTRIDE];
            al[2] = Hlo[base + 4];            al[3] = Hlo[base + 8 * HSTRIDE + 4];
            #pragma unroll
            for (int nt = 0; nt < 16; nt++) {
                uint2 bh = W1ph[(kt * 16 + nt) * 32 + lane];
                uint2 bl = W1pl[(kt * 16 + nt) * 32 + lane];
                mma_bf16(d1[nt], ah, bh);
                mma_bf16(d1[nt], al, bh);
                mma_bf16(d1[nt], ah, bl);
            }
        }

        // ---- GEMM2: softplus(D1) stays in registers as A-frags ----
        float d2[8][4];
        #pragma unroll
        for (int nt = 0; nt < 8; nt++) {
            float2 bb = *(const float2*)&b2s[nt * 8 + 2 * tig];
            d2[nt][0] = bb.x; d2[nt][1] = bb.y; d2[nt][2] = bb.x; d2[nt][3] = bb.y;
        }
        #pragma unroll
        for (int kt = 0; kt < 8; kt++) {
            // A-frag pairs 8kt+tig (nt=2kt) and 8kt+4+tig (nt=2kt+1), rows g / g+8
            unsigned ah[4], al[4];
            split_pair(softplus_f(d1[2 * kt][0]),     softplus_f(d1[2 * kt][1]),     ah[0], al[0]);
            split_pair(softplus_f(d1[2 * kt][2]),     softplus_f(d1[2 * kt][3]),     ah[1], al[1]);
            split_pair(softplus_f(d1[2 * kt + 1][0]), softplus_f(d1[2 * kt + 1][1]), ah[2], al[2]);
            split_pair(softplus_f(d1[2 * kt + 1][2]), softplus_f(d1[2 * kt + 1][3]), ah[3], al[3]);
            #pragma unroll
            for (int nt = 0; nt < 8; nt++) {
                uint2 bh = W2ph[(kt * 8 + nt) * 32 + lane];
                uint2 bl = W2pl[(kt * 8 + nt) * 32 + lane];
                mma_bf16(d2[nt], ah, bh);
                mma_bf16(d2[nt], al, bh);
                mma_bf16(d2[nt], ah, bl);
            }
        }

        // ---- scatter-add (bias already in d2 init) ----
        {
            int r0 = __shfl_sync(0xffffffffu, idx, g);
            int r1 = __shfl_sync(0xffffffffu, idx, g + 8);
            float* o0 = out + (size_t)r0 * DOUT + 2 * tig;
            float* o1 = out + (size_t)r1 * DOUT + 2 * tig;
            #pragma unroll
            for (int nt = 0; nt < 8; nt++) {
                red_add_f2(o0 + nt * 8, d2[nt][0], d2[nt][1]);
                red_add_f2(o1 + nt * 8, d2[nt][2], d2[nt][3]);
            }
        }
        __syncwarp();  // protect warp-private H planes before next tile
    }
}

extern "C" void kernel_launch(void* const* d_in, const int* in_sizes, int n_in,
                              void* d_out, int out_size) {
    // Inputs: x, edge_idx(int32), W0, b0, W1, b1, W2, b2
    const float* x = (const float*)d_in[0];
    const int* eidx = (const int*)d_in[1];
    const float* W0 = (const float*)d_in[2];
    const float* b0 = (const float*)d_in[3];
    const float* W1 = (const float*)d_in[4];
    const float* b1 = (const float*)d_in[5];
    const float* W2 = (const float*)d_in[6];
    const float* b2 = (const float*)d_in[7];
    float* out = (float*)d_out;

    const int pre_smem = (2 * DIN * DH + DH) * sizeof(float);
    cudaFuncSetAttribute(precompute_kernel, cudaFuncAttributeMaxDynamicSharedMemorySize, pre_smem);
    cudaFuncSetAttribute(edge_kernel, cudaFuncAttributeMaxDynamicSharedMemorySize, SM_TOTAL);

    zero_out_kernel<<<(out_size + 255) / 256, 256>>>(out, out_size);
    precompute_kernel<<<296, 256, pre_smem>>>(x, W0, b0);
    edge_kernel<<<148, 256, SM_TOTAL>>>(eidx, W1, b1, W2, b2, out);
}

// round 14
// speedup vs baseline: 3.4038x; 1.2276x over previous
#include <cuda_runtime.h>
#include <cuda_fp16.h>
#include <math.h>

#define N_NODES 50000
#define N_EDGES 800000
#define DIN 64
#define DH 128
#define DOUT 64
#define NWARPS 12
#define THREADS 384
#define NWTILES (N_EDGES / 16)       // 50000 warp-tiles of 16 edges
#define HSTRIDE 68                   // u32 pair-stride per H row (A-frag banks 4g+tig, conflict-free)

// ---- edge-kernel SMEM layout (bytes) ----
#define SM_W1H 0                      // 8kt*16nt*32 uint2 = 32768
#define SM_W2H 32768                  // 8kt*8nt*32 uint2 = 16384
#define SM_HHI 49152                  // 12*16*68*4 = 52224
#define SM_HLO 101376                 // 52224
#define SM_B1  153600                 // 128 f32
#define SM_B2  154112                 // 64 f32
#define SM_TOTAL 154368

// Per-node factored layer-0 partials (A = x@W0[:64], B = x@W0[64:] + b0), fp32 exact.
__device__ float4 g_A4[N_NODES * DH / 4];
__device__ float4 g_B4[N_NODES * DH / 4];

__device__ __forceinline__ float softplus_f(float x) {
    return fmaxf(x, 0.0f) + __logf(1.0f + __expf(-fabsf(x)));
}
// pack two f32 into f16x2: lo half = a (even k), hi half = b (odd k)
__device__ __forceinline__ unsigned pack_h2(float a, float b) {
    unsigned d; asm("cvt.rn.f16x2.f32 %0, %1, %2;" : "=r"(d) : "f"(b), "f"(a)); return d;
}
// hi/lo fp16 split of a k-pair (lo = residual)
__device__ __forceinline__ void split_pair(float h0, float h1, unsigned& hi, unsigned& lo) {
    hi = pack_h2(h0, h1);
    float2 q = __half22float2(*(__half2*)&hi);   // .x = lo half = h0-rounded
    lo = pack_h2(h0 - q.x, h1 - q.y);
}
// m16n8k16 row.col f32.f16.f16.f32 (baseline ISA -> HW HMMA on sm_103)
__device__ __forceinline__ void mma_f16(float* d, const unsigned* a, uint2 b) {
    asm volatile(
        "mma.sync.aligned.m16n8k16.row.col.f32.f16.f16.f32 "
        "{%0,%1,%2,%3}, {%4,%5,%6,%7}, {%8,%9}, {%0,%1,%2,%3};"
        : "+f"(d[0]), "+f"(d[1]), "+f"(d[2]), "+f"(d[3])
        : "r"(a[0]), "r"(a[1]), "r"(a[2]), "r"(a[3]), "r"(b.x), "r"(b.y));
}
__device__ __forceinline__ void red_add_f2(float* p, float x, float y) {
    asm volatile("red.global.add.v2.f32 [%0], {%1,%2};" :: "l"(p), "f"(x), "f"(y) : "memory");
}

__global__ void zero_out_kernel(float* __restrict__ out, int n) {
    int i = blockIdx.x * blockDim.x + threadIdx.x;
    if (i < n) out[i] = 0.0f;
}

// Per-node precompute (fp32 exact): A[n] = x[n]@W0[:64], B[n] = x[n]@W0[64:] + b0
__global__ __launch_bounds__(256, 2)
void precompute_kernel(const float* __restrict__ x,
                       const float* __restrict__ W0,
                       const float* __restrict__ b0) {
    extern __shared__ float smem[];
    float* W0s = smem;
    float* b0s = smem + 2 * DIN * DH;
    for (int i = threadIdx.x; i < 2 * DIN * DH; i += blockDim.x) W0s[i] = W0[i];
    for (int i = threadIdx.x; i < DH; i += blockDim.x) b0s[i] = b0[i];
    __syncthreads();

    const int lane = threadIdx.x & 31;
    const int warp = threadIdx.x >> 5;
    const int nwarps = blockDim.x >> 5;
    float* gA = (float*)g_A4;
    float* gB = (float*)g_B4;

    for (int n = blockIdx.x * nwarps + warp; n < N_NODES; n += gridDim.x * nwarps) {
        float xr[2];
        xr[0] = x[n * DIN + lane];
        xr[1] = x[n * DIN + 32 + lane];
        float accA[4], accB[4];
        #pragma unroll
        for (int u = 0; u < 4; u++) { accA[u] = 0.0f; accB[u] = b0s[lane + 32 * u]; }
        for (int t = 0; t < 32; t++) {
            #pragma unroll
            for (int s = 0; s < 2; s++) {
                float xv = __shfl_sync(0xffffffffu, xr[s], t);
                int k = s * 32 + t;
                #pragma unroll
                for (int u = 0; u < 4; u++) {
                    accA[u] += xv * W0s[k * DH + lane + 32 * u];
                    accB[u] += xv * W0s[(64 + k) * DH + lane + 32 * u];
                }
            }
        }
        #pragma unroll
        for (int u = 0; u < 4; u++) {
            gA[(size_t)n * DH + lane + 32 * u] = accA[u];
            gB[(size_t)n * DH + lane + 32 * u] = accB[u];
        }
    }
}

// Edge kernel: one warp-tile = 16 edges, warps fully independent (no block syncs in loop).
// H0 = softplus(A[r]+B[c]) -> fp16 hi + residual lo planes (warp-private smem);
// GEMM1 2-term fp16 HMMA -> D1 regs; softplus -> A-frags in regs; GEMM2 2-term -> scatter.
__global__ __launch_bounds__(THREADS, 1)
void edge_kernel(const int* __restrict__ eidx,
                 const float* __restrict__ W1,
                 const float* __restrict__ b1,
                 const float* __restrict__ W2,
                 const float* __restrict__ b2,
                 float* __restrict__ out) {
    extern __shared__ unsigned char smem_uc[];
    uint2* W1ph = (uint2*)(smem_uc + SM_W1H);
    uint2* W2ph = (uint2*)(smem_uc + SM_W2H);
    unsigned* Hhi = (unsigned*)(smem_uc + SM_HHI);
    unsigned* Hlo = (unsigned*)(smem_uc + SM_HLO);
    float* b1s = (float*)(smem_uc + SM_B1);
    float* b2s = (float*)(smem_uc + SM_B2);

    const int tid = threadIdx.x;
    const int lane = tid & 31;
    const int w = tid >> 5;
    const int g = lane >> 2;    // fragment group (row-in-8)
    const int tig = lane & 3;   // thread-in-group
    const int mb = 16 * w;      // warp's private 16-row block in H planes

    // ---- one-time weight prep: fp16-rounded b-fragments, 1 uint2 per (kt,nt,lane) ----
    for (int i = tid; i < 8 * 16 * 32; i += THREADS) {
        int li = i & 31, nt = (i >> 5) & 15, kt = i >> 9;
        int k0 = kt * 16 + 2 * (li & 3), n = nt * 8 + (li >> 2);
        uint2 hi;
        hi.x = pack_h2(W1[k0 * DH + n],       W1[(k0 + 1) * DH + n]);
        hi.y = pack_h2(W1[(k0 + 8) * DH + n], W1[(k0 + 9) * DH + n]);
        W1ph[i] = hi;
    }
    for (int i = tid; i < 8 * 8 * 32; i += THREADS) {
        int li = i & 31, nt = (i >> 5) & 7, kt = i >> 8;
        int k0 = kt * 16 + 2 * (li & 3), n = nt * 8 + (li >> 2);
        uint2 hi;
        hi.x = pack_h2(W2[k0 * DOUT + n],       W2[(k0 + 1) * DOUT + n]);
        hi.y = pack_h2(W2[(k0 + 8) * DOUT + n], W2[(k0 + 9) * DOUT + n]);
        W2ph[i] = hi;
    }
    if (tid < DH) b1s[tid] = b1[tid];
    if (tid < DOUT) b2s[tid] = b2[tid];
    __syncthreads();

    for (int wt = blockIdx.x * NWARPS + w; wt < NWTILES; wt += gridDim.x * NWARPS) {
        const int e0 = wt * 16;
        // lanes 0-15: row idx, lanes 16-31: col idx
        int idx = (lane < 16) ? eidx[e0 + lane] : eidx[N_EDGES + e0 + (lane - 16)];

        // ---- gather + softplus + fp16 hi/lo split -> warp-private H planes ----
        #pragma unroll 4
        for (int i = 0; i < 16; i++) {
            int r = __shfl_sync(0xffffffffu, idx, i);
            int c = __shfl_sync(0xffffffffu, idx, 16 + i);
            float4 a = g_A4[(size_t)r * 32 + lane];
            float4 b = g_B4[(size_t)c * 32 + lane];
            float h0 = softplus_f(a.x + b.x);
            float h1 = softplus_f(a.y + b.y);
            float h2 = softplus_f(a.z + b.z);
            float h3 = softplus_f(a.w + b.w);
            uint2 hi, lo;
            split_pair(h0, h1, hi.x, lo.x);
            split_pair(h2, h3, hi.y, lo.y);
            *(uint2*)&Hhi[(mb + i) * HSTRIDE + 2 * lane] = hi;
            *(uint2*)&Hlo[(mb + i) * HSTRIDE + 2 * lane] = lo;
        }
        __syncwarp();

        // ---- GEMM1: D1[16 x 128] = H0 @ W1 + b1 (2-term: Hhi*W + Hlo*W) ----
        float d1[16][4];
        #pragma unroll
        for (int nt = 0; nt < 16; nt++) {
            float2 bb = *(const float2*)&b1s[nt * 8 + 2 * tig];
            d1[nt][0] = bb.x; d1[nt][1] = bb.y; d1[nt][2] = bb.x; d1[nt][3] = bb.y;
        }
        #pragma unroll
        for (int kt = 0; kt < 8; kt++) {
            int base = (mb + g) * HSTRIDE + 8 * kt + tig;
            unsigned ah[4], al[4];
            ah[0] = Hhi[base];     ah[1] = Hhi[base + 8 * HSTRIDE];
            ah[2] = Hhi[base + 4]; ah[3] = Hhi[base + 8 * HSTRIDE + 4];
            al[0] = Hlo[base];     al[1] = Hlo[base + 8 * HSTRIDE];
            al[2] = Hlo[base + 4]; al[3] = Hlo[base + 8 * HSTRIDE + 4];
            #pragma unroll
            for (int nt = 0; nt < 16; nt++) {
                uint2 bh = W1ph[(kt * 16 + nt) * 32 + lane];
                mma_f16(d1[nt], ah, bh);
                mma_f16(d1[nt], al, bh);
            }
        }

        // ---- GEMM2: softplus(D1) stays in registers as A-frags (2-term) ----
        float d2[8][4];
        #pragma unroll
        for (int nt = 0; nt < 8; nt++) {
            float2 bb = *(const float2*)&b2s[nt * 8 + 2 * tig];
            d2[nt][0] = bb.x; d2[nt][1] = bb.y; d2[nt][2] = bb.x; d2[nt][3] = bb.y;
        }
        #pragma unroll
        for (int kt = 0; kt < 8; kt++) {
            // A-frag pairs 8kt+tig (from d1[2kt]) and 8kt+4+tig (from d1[2kt+1]), rows g / g+8
            unsigned ah[4], al[4];
            split_pair(softplus_f(d1[2 * kt][0]),     softplus_f(d1[2 * kt][1]),     ah[0], al[0]);
            split_pair(softplus_f(d1[2 * kt][2]),     softplus_f(d1[2 * kt][3]),     ah[1], al[1]);
            split_pair(softplus_f(d1[2 * kt + 1][0]), softplus_f(d1[2 * kt + 1][1]), ah[2], al[2]);
            split_pair(softplus_f(d1[2 * kt + 1][2]), softplus_f(d1[2 * kt + 1][3]), ah[3], al[3]);
            #pragma unroll
            for (int nt = 0; nt < 8; nt++) {
                uint2 bh = W2ph[(kt * 8 + nt) * 32 + lane];
                mma_f16(d2[nt], ah, bh);
                mma_f16(d2[nt], al, bh);
            }
        }

        // ---- scatter-add (bias already in d2 init) ----
        {
            int r0 = __shfl_sync(0xffffffffu, idx, g);
            int r1 = __shfl_sync(0xffffffffu, idx, g + 8);
            float* o0 = out + (size_t)r0 * DOUT + 2 * tig;
            float* o1 = out + (size_t)r1 * DOUT + 2 * tig;
            #pragma unroll
            for (int nt = 0; nt < 8; nt++) {
                red_add_f2(o0 + nt * 8, d2[nt][0], d2[nt][1]);
                red_add_f2(o1 + nt * 8, d2[nt][2], d2[nt][3]);
            }
        }
        __syncwarp();  // protect warp-private H planes before next tile
    }
}

extern "C" void kernel_launch(void* const* d_in, const int* in_sizes, int n_in,
                              void* d_out, int out_size) {
    // Inputs: x, edge_idx(int32), W0, b0, W1, b1, W2, b2
    const float* x = (const float*)d_in[0];
    const int* eidx = (const int*)d_in[1];
    const float* W0 = (const float*)d_in[2];
    const float* b0 = (const float*)d_in[3];
    const float* W1 = (const float*)d_in[4];
    const float* b1 = (const float*)d_in[5];
    const float* W2 = (const float*)d_in[6];
    const float* b2 = (const float*)d_in[7];
    float* out = (float*)d_out;

    const int pre_smem = (2 * DIN * DH + DH) * sizeof(float);
    cudaFuncSetAttribute(precompute_kernel, cudaFuncAttributeMaxDynamicSharedMemorySize, pre_smem);
    cudaFuncSetAttribute(edge_kernel, cudaFuncAttributeMaxDynamicSharedMemorySize, SM_TOTAL);

    zero_out_kernel<<<(out_size + 255) / 256, 256>>>(out, out_size);
    precompute_kernel<<<296, 256, pre_smem>>>(x, W0, b0);
    edge_kernel<<<148, THREADS, SM_TOTAL>>>(eidx, W1, b1, W2, b2, out);
}

// round 15
// speedup vs baseline: 4.0839x; 1.1998x over previous
#include <cuda_runtime.h>
#include <cuda_fp16.h>
#include <math.h>

#define N_NODES 50000
#define N_EDGES 800000
#define DIN 64
#define DH 128
#define DOUT 64
#define NWARPS 12
#define THREADS 384
#define NWTILES (N_EDGES / 16)       // 50000 warp-tiles of 16 edges
#define HSTRIDE 68                   // u32 pair-stride per H row (A-frag banks 4g+tig, conflict-free)

// ---- edge-kernel SMEM layout (bytes) ----
#define SM_W1H 0                      // 8kt*16nt*32 uint2 = 32768
#define SM_W2H 32768                  // 8kt*8nt*32 uint2 = 16384
#define SM_HHI 49152                  // 12*16*68*4 = 52224
#define SM_B1  101376                 // 128 f32
#define SM_B2  101888                 // 64 f32
#define SM_TOTAL 102144

// Per-node factored layer-0 partials (A = x@W0[:64], B = x@W0[64:] + b0), fp32 exact.
__device__ float4 g_A4[N_NODES * DH / 4];
__device__ float4 g_B4[N_NODES * DH / 4];

__device__ __forceinline__ float softplus_f(float x) {
    return fmaxf(x, 0.0f) + __logf(1.0f + __expf(-fabsf(x)));
}
// pack two f32 into f16x2: lo half = a (even k), hi half = b (odd k)
__device__ __forceinline__ unsigned pack_h2(float a, float b) {
    unsigned d; asm("cvt.rn.f16x2.f32 %0, %1, %2;" : "=r"(d) : "f"(b), "f"(a)); return d;
}
// m16n8k16 row.col f32.f16.f16.f32 (baseline ISA -> HW HMMA on sm_103)
__device__ __forceinline__ void mma_f16(float* d, const unsigned* a, uint2 b) {
    asm volatile(
        "mma.sync.aligned.m16n8k16.row.col.f32.f16.f16.f32 "
        "{%0,%1,%2,%3}, {%4,%5,%6,%7}, {%8,%9}, {%0,%1,%2,%3};"
        : "+f"(d[0]), "+f"(d[1]), "+f"(d[2]), "+f"(d[3])
        : "r"(a[0]), "r"(a[1]), "r"(a[2]), "r"(a[3]), "r"(b.x), "r"(b.y));
}
__device__ __forceinline__ void red_add_f2(float* p, float x, float y) {
    asm volatile("red.global.add.v2.f32 [%0], {%1,%2};" :: "l"(p), "f"(x), "f"(y) : "memory");
}

__global__ void zero_out_kernel(float* __restrict__ out, int n) {
    int i = blockIdx.x * blockDim.x + threadIdx.x;
    if (i < n) out[i] = 0.0f;
}

// Per-node precompute (fp32 exact): A[n] = x[n]@W0[:64], B[n] = x[n]@W0[64:] + b0
__global__ __launch_bounds__(256, 2)
void precompute_kernel(const float* __restrict__ x,
                       const float* __restrict__ W0,
                       const float* __restrict__ b0) {
    extern __shared__ float smem[];
    float* W0s = smem;
    float* b0s = smem + 2 * DIN * DH;
    for (int i = threadIdx.x; i < 2 * DIN * DH; i += blockDim.x) W0s[i] = W0[i];
    for (int i = threadIdx.x; i < DH; i += blockDim.x) b0s[i] = b0[i];
    __syncthreads();

    const int lane = threadIdx.x & 31;
    const int warp = threadIdx.x >> 5;
    const int nwarps = blockDim.x >> 5;
    float* gA = (float*)g_A4;
    float* gB = (float*)g_B4;

    for (int n = blockIdx.x * nwarps + warp; n < N_NODES; n += gridDim.x * nwarps) {
        float xr[2];
        xr[0] = x[n * DIN + lane];
        xr[1] = x[n * DIN + 32 + lane];
        float accA[4], accB[4];
        #pragma unroll
        for (int u = 0; u < 4; u++) { accA[u] = 0.0f; accB[u] = b0s[lane + 32 * u]; }
        for (int t = 0; t < 32; t++) {
            #pragma unroll
            for (int s = 0; s < 2; s++) {
                float xv = __shfl_sync(0xffffffffu, xr[s], t);
                int k = s * 32 + t;
                #pragma unroll
                for (int u = 0; u < 4; u++) {
                    accA[u] += xv * W0s[k * DH + lane + 32 * u];
                    accB[u] += xv * W0s[(64 + k) * DH + lane + 32 * u];
                }
            }
        }
        #pragma unroll
        for (int u = 0; u < 4; u++) {
            gA[(size_t)n * DH + lane + 32 * u] = accA[u];
            gB[(size_t)n * DH + lane + 32 * u] = accB[u];
        }
    }
}

// Edge kernel: one warp-tile = 16 edges, warps fully independent (no block syncs in loop).
// H0 = softplus(A[r]+B[c]) -> fp16 plane (warp-private smem);
// GEMM1 1-term fp16 HMMA -> D1 regs; softplus -> A-frags in regs; GEMM2 1-term -> scatter.
__global__ __launch_bounds__(THREADS, 1)
void edge_kernel(const int* __restrict__ eidx,
                 const float* __restrict__ W1,
                 const float* __restrict__ b1,
                 const float* __restrict__ W2,
                 const float* __restrict__ b2,
                 float* __restrict__ out) {
    extern __shared__ unsigned char smem_uc[];
    uint2* W1ph = (uint2*)(smem_uc + SM_W1H);
    uint2* W2ph = (uint2*)(smem_uc + SM_W2H);
    unsigned* Hhi = (unsigned*)(smem_uc + SM_HHI);
    float* b1s = (float*)(smem_uc + SM_B1);
    float* b2s = (float*)(smem_uc + SM_B2);

    const int tid = threadIdx.x;
    const int lane = tid & 31;
    const int w = tid >> 5;
    const int g = lane >> 2;    // fragment group (row-in-8)
    const int tig = lane & 3;   // thread-in-group
    const int mb = 16 * w;      // warp's private 16-row block in H plane

    // ---- one-time weight prep: fp16-rounded b-fragments, 1 uint2 per (kt,nt,lane) ----
    for (int i = tid; i < 8 * 16 * 32; i += THREADS) {
        int li = i & 31, nt = (i >> 5) & 15, kt = i >> 9;
        int k0 = kt * 16 + 2 * (li & 3), n = nt * 8 + (li >> 2);
        uint2 hi;
        hi.x = pack_h2(W1[k0 * DH + n],       W1[(k0 + 1) * DH + n]);
        hi.y = pack_h2(W1[(k0 + 8) * DH + n], W1[(k0 + 9) * DH + n]);
        W1ph[i] = hi;
    }
    for (int i = tid; i < 8 * 8 * 32; i += THREADS) {
        int li = i & 31, nt = (i >> 5) & 7, kt = i >> 8;
        int k0 = kt * 16 + 2 * (li & 3), n = nt * 8 + (li >> 2);
        uint2 hi;
        hi.x = pack_h2(W2[k0 * DOUT + n],       W2[(k0 + 1) * DOUT + n]);
        hi.y = pack_h2(W2[(k0 + 8) * DOUT + n], W2[(k0 + 9) * DOUT + n]);
        W2ph[i] = hi;
    }
    if (tid < DH) b1s[tid] = b1[tid];
    if (tid < DOUT) b2s[tid] = b2[tid];
    __syncthreads();

    for (int wt = blockIdx.x * NWARPS + w; wt < NWTILES; wt += gridDim.x * NWARPS) {
        const int e0 = wt * 16;
        // lanes 0-15: row idx, lanes 16-31: col idx
        int idx = (lane < 16) ? eidx[e0 + lane] : eidx[N_EDGES + e0 + (lane - 16)];

        // ---- gather + softplus + fp16 pack -> warp-private H plane ----
        #pragma unroll 4
        for (int i = 0; i < 16; i++) {
            int r = __shfl_sync(0xffffffffu, idx, i);
            int c = __shfl_sync(0xffffffffu, idx, 16 + i);
            float4 a = g_A4[(size_t)r * 32 + lane];
            float4 b = g_B4[(size_t)c * 32 + lane];
            uint2 hi;
            hi.x = pack_h2(softplus_f(a.x + b.x), softplus_f(a.y + b.y));
            hi.y = pack_h2(softplus_f(a.z + b.z), softplus_f(a.w + b.w));
            *(uint2*)&Hhi[(mb + i) * HSTRIDE + 2 * lane] = hi;
        }
        __syncwarp();

        // ---- GEMM1: D1[16 x 128] = H0 @ W1 + b1 (1-term fp16) ----
        float d1[16][4];
        #pragma unroll
        for (int nt = 0; nt < 16; nt++) {
            float2 bb = *(const float2*)&b1s[nt * 8 + 2 * tig];
            d1[nt][0] = bb.x; d1[nt][1] = bb.y; d1[nt][2] = bb.x; d1[nt][3] = bb.y;
        }
        #pragma unroll
        for (int kt = 0; kt < 8; kt++) {
            int base = (mb + g) * HSTRIDE + 8 * kt + tig;
            unsigned ah[4];
            ah[0] = Hhi[base];     ah[1] = Hhi[base + 8 * HSTRIDE];
            ah[2] = Hhi[base + 4]; ah[3] = Hhi[base + 8 * HSTRIDE + 4];
            #pragma unroll
            for (int nt = 0; nt < 16; nt++) {
                uint2 bh = W1ph[(kt * 16 + nt) * 32 + lane];
                mma_f16(d1[nt], ah, bh);
            }
        }

        // ---- GEMM2: softplus(D1) stays in registers as A-frags (1-term) ----
        float d2[8][4];
        #pragma unroll
        for (int nt = 0; nt < 8; nt++) {
            float2 bb = *(const float2*)&b2s[nt * 8 + 2 * tig];
            d2[nt][0] = bb.x; d2[nt][1] = bb.y; d2[nt][2] = bb.x; d2[nt][3] = bb.y;
        }
        #pragma unroll
        for (int kt = 0; kt < 8; kt++) {
            // A-frag pairs 8kt+tig (from d1[2kt]) and 8kt+4+tig (from d1[2kt+1]), rows g / g+8
            unsigned ah[4];
            ah[0] = pack_h2(softplus_f(d1[2 * kt][0]),     softplus_f(d1[2 * kt][1]));
            ah[1] = pack_h2(softplus_f(d1[2 * kt][2]),     softplus_f(d1[2 * kt][3]));
            ah[2] = pack_h2(softplus_f(d1[2 * kt + 1][0]), softplus_f(d1[2 * kt + 1][1]));
            ah[3] = pack_h2(softplus_f(d1[2 * kt + 1][2]), softplus_f(d1[2 * kt + 1][3]));
            #pragma unroll
            for (int nt = 0; nt < 8; nt++) {
                uint2 bh = W2ph[(kt * 8 + nt) * 32 + lane];
                mma_f16(d2[nt], ah, bh);
            }
        }

        // ---- scatter-add (bias already in d2 init) ----
        {
            int r0 = __shfl_sync(0xffffffffu, idx, g);
            int r1 = __shfl_sync(0xffffffffu, idx, g + 8);
            float* o0 = out + (size_t)r0 * DOUT + 2 * tig;
            float* o1 = out + (size_t)r1 * DOUT + 2 * tig;
            #pragma unroll
            for (int nt = 0; nt < 8; nt++) {
                red_add_f2(o0 + nt * 8, d2[nt][0], d2[nt][1]);
                red_add_f2(o1 + nt * 8, d2[nt][2], d2[nt][3]);
            }
        }
        __syncwarp();  // protect warp-private H plane before next tile
    }
}

extern "C" void kernel_launch(void* const* d_in, const int* in_sizes, int n_in,
                              void* d_out, int out_size) {
    // Inputs: x, edge_idx(int32), W0, b0, W1, b1, W2, b2
    const float* x = (const float*)d_in[0];
    const int* eidx = (const int*)d_in[1];
    const float* W0 = (const float*)d_in[2];
    const float* b0 = (const float*)d_in[3];
    const float* W1 = (const float*)d_in[4];
    const float* b1 = (const float*)d_in[5];
    const float* W2 = (const float*)d_in[6];
    const float* b2 = (const float*)d_in[7];
    float* out = (float*)d_out;

    const int pre_smem = (2 * DIN * DH + DH) * sizeof(float);
    cudaFuncSetAttribute(precompute_kernel, cudaFuncAttributeMaxDynamicSharedMemorySize, pre_smem);
    cudaFuncSetAttribute(edge_kernel, cudaFuncAttributeMaxDynamicSharedMemorySize, SM_TOTAL);

    zero_out_kernel<<<(out_size + 255) / 256, 256>>>(out, out_size);
    precompute_kernel<<<296, 256, pre_smem>>>(x, W0, b0);
    edge_kernel<<<148, THREADS, SM_TOTAL>>>(eidx, W1, b1, W2, b2, out);
}

// round 17
// speedup vs baseline: 4.4834x; 1.0978x over previous
#include <cuda_runtime.h>
#include <cuda_fp16.h>
#include <math.h>

#define N_NODES 50000
#define N_EDGES 800000
#define DIN 64
#define DH 128
#define DOUT 64
#define NWARPS 16
#define THREADS 512
#define NWTILES (N_EDGES / 16)       // 50000 warp-tiles of 16 edges
#define HSTRIDE 68                   // u32 pair-stride per H row (A-frag banks 4g+tig, conflict-free)

// ---- edge-kernel SMEM layout (bytes) ----
#define SM_W1H 0                      // 8kt*16nt*32 uint2 = 32768
#define SM_W2H 32768                  // 8kt*8nt*32 uint2 = 16384
#define SM_HHI 49152                  // 16*16*68*4 = 69632
#define SM_B1  118784                 // 128 f32
#define SM_B2  119296                 // 64 f32
#define SM_TOTAL 119552

// Per-node factored layer-0 partials (A = x@W0[:64], B = x@W0[64:] + b0), fp32 exact.
__device__ float4 g_A4[N_NODES * DH / 4];
__device__ float4 g_B4[N_NODES * DH / 4];

__device__ __forceinline__ float softplus_f(float x) {
    return fmaxf(x, 0.0f) + __logf(1.0f + __expf(-fabsf(x)));
}
// pack two f32 into f16x2: lo half = a (even k), hi half = b (odd k)
__device__ __forceinline__ unsigned pack_h2(float a, float b) {
    unsigned d; asm("cvt.rn.f16x2.f32 %0, %1, %2;" : "=r"(d) : "f"(b), "f"(a)); return d;
}
// m16n8k16 row.col f32.f16.f16.f32 (baseline ISA -> HW HMMA on sm_103)
__device__ __forceinline__ void mma_f16(float* d, const unsigned* a, uint2 b) {
    asm volatile(
        "mma.sync.aligned.m16n8k16.row.col.f32.f16.f16.f32 "
        "{%0,%1,%2,%3}, {%4,%5,%6,%7}, {%8,%9}, {%0,%1,%2,%3};"
        : "+f"(d[0]), "+f"(d[1]), "+f"(d[2]), "+f"(d[3])
        : "r"(a[0]), "r"(a[1]), "r"(a[2]), "r"(a[3]), "r"(b.x), "r"(b.y));
}
__device__ __forceinline__ void red_add_f2(float* p, float x, float y) {
    asm volatile("red.global.add.v2.f32 [%0], {%1,%2};" :: "l"(p), "f"(x), "f"(y) : "memory");
}

__global__ void zero_out_kernel(float* __restrict__ out, int n) {
    int i = blockIdx.x * blockDim.x + threadIdx.x;
    if (i < n) out[i] = 0.0f;
}

// Per-node precompute (fp32 exact): A[n] = x[n]@W0[:64], B[n] = x[n]@W0[64:] + b0
__global__ __launch_bounds__(256, 2)
void precompute_kernel(const float* __restrict__ x,
                       const float* __restrict__ W0,
                       const float* __restrict__ b0) {
    extern __shared__ float smem[];
    float* W0s = smem;
    float* b0s = smem + 2 * DIN * DH;
    for (int i = threadIdx.x; i < 2 * DIN * DH; i += blockDim.x) W0s[i] = W0[i];
    for (int i = threadIdx.x; i < DH; i += blockDim.x) b0s[i] = b0[i];
    __syncthreads();

    const int lane = threadIdx.x & 31;
    const int warp = threadIdx.x >> 5;
    const int nwarps = blockDim.x >> 5;
    float* gA = (float*)g_A4;
    float* gB = (float*)g_B4;

    for (int n = blockIdx.x * nwarps + warp; n < N_NODES; n += gridDim.x * nwarps) {
        float xr[2];
        xr[0] = x[n * DIN + lane];
        xr[1] = x[n * DIN + 32 + lane];
        float accA[4], accB[4];
        #pragma unroll
        for (int u = 0; u < 4; u++) { accA[u] = 0.0f; accB[u] = b0s[lane + 32 * u]; }
        for (int t = 0; t < 32; t++) {
            #pragma unroll
            for (int s = 0; s < 2; s++) {
                float xv = __shfl_sync(0xffffffffu, xr[s], t);
                int k = s * 32 + t;
                #pragma unroll
                for (int u = 0; u < 4; u++) {
                    accA[u] += xv * W0s[k * DH + lane + 32 * u];
                    accB[u] += xv * W0s[(64 + k) * DH + lane + 32 * u];
                }
            }
        }
        #pragma unroll
        for (int u = 0; u < 4; u++) {
            gA[(size_t)n * DH + lane + 32 * u] = accA[u];
            gB[(size_t)n * DH + lane + 32 * u] = accB[u];
        }
    }
}

// Edge kernel: one warp-tile = 16 edges, warps fully independent (no block syncs in loop).
// 16 warps / 512 threads; GEMM1 split into two nt-halves so d1 uses only 32 live regs,
// each half immediately folded into GEMM2 accumulation (d2) -> fits 128 regs/thread.
__global__ __launch_bounds__(THREADS, 1)
void edge_kernel(const int* __restrict__ eidx,
                 const float* __restrict__ W1,
                 const float* __restrict__ b1,
                 const float* __restrict__ W2,
                 const float* __restrict__ b2,
                 float* __restrict__ out) {
    extern __shared__ unsigned char smem_uc[];
    uint2* W1ph = (uint2*)(smem_uc + SM_W1H);
    uint2* W2ph = (uint2*)(smem_uc + SM_W2H);
    unsigned* Hhi = (unsigned*)(smem_uc + SM_HHI);
    float* b1s = (float*)(smem_uc + SM_B1);
    float* b2s = (float*)(smem_uc + SM_B2);

    const int tid = threadIdx.x;
    const int lane = tid & 31;
    const int w = tid >> 5;
    const int g = lane >> 2;    // fragment group (row-in-8)
    const int tig = lane & 3;   // thread-in-group
    const int mb = 16 * w;      // warp's private 16-row block in H plane

    // ---- one-time weight prep: fp16-rounded b-fragments, 1 uint2 per (kt,nt,lane) ----
    for (int i = tid; i < 8 * 16 * 32; i += THREADS) {
        int li = i & 31, nt = (i >> 5) & 15, kt = i >> 9;
        int k0 = kt * 16 + 2 * (li & 3), n = nt * 8 + (li >> 2);
        uint2 hi;
        hi.x = pack_h2(W1[k0 * DH + n],       W1[(k0 + 1) * DH + n]);
        hi.y = pack_h2(W1[(k0 + 8) * DH + n], W1[(k0 + 9) * DH + n]);
        W1ph[i] = hi;
    }
    for (int i = tid; i < 8 * 8 * 32; i += THREADS) {
        int li = i & 31, nt = (i >> 5) & 7, kt = i >> 8;
        int k0 = kt * 16 + 2 * (li & 3), n = nt * 8 + (li >> 2);
        uint2 hi;
        hi.x = pack_h2(W2[k0 * DOUT + n],       W2[(k0 + 1) * DOUT + n]);
        hi.y = pack_h2(W2[(k0 + 8) * DOUT + n], W2[(k0 + 9) * DOUT + n]);
        W2ph[i] = hi;
    }
    if (tid < DH) b1s[tid] = b1[tid];
    if (tid < DOUT) b2s[tid] = b2[tid];
    __syncthreads();

    for (int wt = blockIdx.x * NWARPS + w; wt < NWTILES; wt += gridDim.x * NWARPS) {
        const int e0 = wt * 16;
        // lanes 0-15: row idx, lanes 16-31: col idx
        int idx = (lane < 16) ? eidx[e0 + lane] : eidx[N_EDGES + e0 + (lane - 16)];

        // ---- gather + softplus + fp16 pack -> warp-private H plane ----
        #pragma unroll 4
        for (int i = 0; i < 16; i++) {
            int r = __shfl_sync(0xffffffffu, idx, i);
            int c = __shfl_sync(0xffffffffu, idx, 16 + i);
            float4 a = g_A4[(size_t)r * 32 + lane];
            float4 b = g_B4[(size_t)c * 32 + lane];
            uint2 hi;
            hi.x = pack_h2(softplus_f(a.x + b.x), softplus_f(a.y + b.y));
            hi.y = pack_h2(softplus_f(a.z + b.z), softplus_f(a.w + b.w));
            *(uint2*)&Hhi[(mb + i) * HSTRIDE + 2 * lane] = hi;
        }
        __syncwarp();

        // ---- d2 accumulators (GEMM2 output), bias-initialized ----
        float d2[8][4];
        #pragma unroll
        for (int nt = 0; nt < 8; nt++) {
            float2 bb = *(const float2*)&b2s[nt * 8 + 2 * tig];
            d2[nt][0] = bb.x; d2[nt][1] = bb.y; d2[nt][2] = bb.x; d2[nt][3] = bb.y;
        }

        // ---- two nt-halves: GEMM1-half -> softplus -> GEMM2 contribution ----
        #pragma unroll
        for (int half = 0; half < 2; half++) {
            float d1h[8][4];   // GEMM1 outputs for nt = 8*half .. 8*half+7
            #pragma unroll
            for (int j = 0; j < 8; j++) {
                float2 bb = *(const float2*)&b1s[(8 * half + j) * 8 + 2 * tig];
                d1h[j][0] = bb.x; d1h[j][1] = bb.y; d1h[j][2] = bb.x; d1h[j][3] = bb.y;
            }
            #pragma unroll
            for (int kt = 0; kt < 8; kt++) {
                int base = (mb + g) * HSTRIDE + 8 * kt + tig;
                unsigned ah[4];
                ah[0] = Hhi[base];     ah[1] = Hhi[base + 8 * HSTRIDE];
                ah[2] = Hhi[base + 4]; ah[3] = Hhi[base + 8 * HSTRIDE + 4];
                #pragma unroll
                for (int j = 0; j < 8; j++) {
                    uint2 bh = W1ph[(kt * 16 + 8 * half + j) * 32 + lane];
                    mma_f16(d1h[j], ah, bh);
                }
            }
            // GEMM2 kt2 = 4*half + j2, consumes d1h[2*j2], d1h[2*j2+1]
            #pragma unroll
            for (int j2 = 0; j2 < 4; j2++) {
                int kt2 = 4 * half + j2;
                unsigned ah[4];
                ah[0] = pack_h2(softplus_f(d1h[2 * j2][0]),     softplus_f(d1h[2 * j2][1]));
                ah[1] = pack_h2(softplus_f(d1h[2 * j2][2]),     softplus_f(d1h[2 * j2][3]));
                ah[2] = pack_h2(softplus_f(d1h[2 * j2 + 1][0]), softplus_f(d1h[2 * j2 + 1][1]));
                ah[3] = pack_h2(softplus_f(d1h[2 * j2 + 1][2]), softplus_f(d1h[2 * j2 + 1][3]));
                #pragma unroll
                for (int nt = 0; nt < 8; nt++) {
                    uint2 bh = W2ph[(kt2 * 8 + nt) * 32 + lane];
                    mma_f16(d2[nt], ah, bh);
                }
            }
        }

        // ---- scatter-add (bias already in d2 init) ----
        {
            int r0 = __shfl_sync(0xffffffffu, idx, g);
            int r1 = __shfl_sync(0xffffffffu, idx, g + 8);
            float* o0 = out + (size_t)r0 * DOUT + 2 * tig;
            float* o1 = out + (size_t)r1 * DOUT + 2 * tig;
            #pragma unroll
            for (int nt = 0; nt < 8; nt++) {
                red_add_f2(o0 + nt * 8, d2[nt][0], d2[nt][1]);
                red_add_f2(o1 + nt * 8, d2[nt][2], d2[nt][3]);
            }
        }
        __syncwarp();  // protect warp-private H plane before next tile
    }
}

extern "C" void kernel_launch(void* const* d_in, const int* in_sizes, int n_in,
                              void* d_out, int out_size) {
    // Inputs: x, edge_idx(int32), W0, b0, W1, b1, W2, b2
    const float* x = (const float*)d_in[0];
    const int* eidx = (const int*)d_in[1];
    const float* W0 = (const float*)d_in[2];
    const float* b0 = (const float*)d_in[3];
    const float* W1 = (const float*)d_in[4];
    const float* b1 = (const float*)d_in[5];
    const float* W2 = (const float*)d_in[6];
    const float* b2 = (const float*)d_in[7];
    float* out = (float*)d_out;

    const int pre_smem = (2 * DIN * DH + DH) * sizeof(float);
    cudaFuncSetAttribute(precompute_kernel, cudaFuncAttributeMaxDynamicSharedMemorySize, pre_smem);
    cudaFuncSetAttribute(edge_kernel, cudaFuncAttributeMaxDynamicSharedMemorySize, SM_TOTAL);

    zero_out_kernel<<<(out_size + 255) / 256, 256>>>(out, out_size);
    precompute_kernel<<<296, 256, pre_smem>>>(x, W0, b0);
    edge_kernel<<<148, THREADS, SM_TOTAL>>>(eidx, W1, b1, W2, b2, out);
}